// round 17
// baseline (speedup 1.0000x reference)
#include <cuda_runtime.h>
#include <cuda_bf16.h>
#include <cstdint>

#define B_ 256
#define N_ 512
#define M_ 1024
#define WARPS_PER_BLOCK 4
#define BLOCKS 888                    // 148 SMs * 6 CTAs, single wave

// FFMA-imm helpers (rt_SMSP=1). fma(a,1.0,b)==a+b, fma(a,-1.0,b)==b-a, bit-exact.
__device__ __forceinline__ float add_via_fma(float a, float b) {
    float d;
    asm("fma.rn.f32 %0, %1, 0f3F800000, %2;" : "=f"(d) : "f"(a), "f"(b));
    return d;
}
__device__ __forceinline__ float rsub_via_fma(float a, float b) {  // b - a
    float d;
    asm("fma.rn.f32 %0, %1, 0fBF800000, %2;" : "=f"(d) : "f"(a), "f"(b));
    return d;
}
__device__ __forceinline__ float fma_l2e(float a, float b) {       // a*log2e + b
    float d;
    asm("fma.rn.f32 %0, %1, 0f3FB8AA3B, %2;" : "=f"(d) : "f"(a), "f"(b));
    return d;
}

// e^(g+l) via exp2, log2e folded into range reduction, magic-round ldexp:
// tsh = fma(z,L2E,MAGIC) puts round(z*log2e) in the low mantissa bits; adding
// (bits<<23) to the poly's float bits is an exact ldexp (low 9 bits of
// 0x4B400000 are zero). Degree-3 economized poly: rel err ~3e-5 (thr 1e-3).
__device__ __forceinline__ float exp_gl(float g, float l) {
    const float MAGIC = 12582912.0f;          // 2^23 + 2^22
    float z   = add_via_fma(g, l);
    float tsh = fma_l2e(z, MAGIC);
    float nrf = rsub_via_fma(tsh, MAGIC);
    float f   = fma_l2e(z, nrf);              // f in [-0.5, 0.5]
    int   bi  = __float_as_int(tsh);
    float p = fmaf(f, 0.05592078f, 0.24263103f);
    p = fmaf(f, p, 0.69312114f);
    p = fmaf(f, p, 0.99992486f);
    return __int_as_float(__float_as_int(p) + (bi << 23));
}

__device__ __forceinline__ void load_row(float4 g[8], const float* __restrict__ gum,
                                         int row, int lane) {
    const float4* __restrict__ g4 = (const float4*)(gum + (size_t)row * M_) + lane;
    #pragma unroll
    for (int i = 0; i < 8; ++i) g[i] = __ldcs(&g4[i * 32]);
}

__device__ __forceinline__ void compute_row(const float4 g[8],
                                            const float* __restrict__ x,
                                            const float* __restrict__ logits,
                                            float* __restrict__ out,
                                            int row, int lane) {
    const int n = row & (N_ - 1);     // % N_
    const int b = row >> 9;           // / N_
    const float4* __restrict__ l4 = (const float4*)(logits + (size_t)n * M_) + lane;
    const float4* __restrict__ x4 = (const float4*)(x + (size_t)b * M_) + lane;

    float s = 0.0f, ws = 0.0f;
    #pragma unroll
    for (int i = 0; i < 8; ++i) {
        float4 lv = __ldg(&l4[i * 32]);   // L2-resident (2 MB table)
        float4 xv = __ldg(&x4[i * 32]);   // L1-hot: b constant across block range

        float e0 = exp_gl(g[i].x, lv.x);
        float e1 = exp_gl(g[i].y, lv.y);
        float e2 = exp_gl(g[i].z, lv.z);
        float e3 = exp_gl(g[i].w, lv.w);

        s = add_via_fma(e0, s); ws = fmaf(e0, xv.x, ws);
        s = add_via_fma(e1, s); ws = fmaf(e1, xv.y, ws);
        s = add_via_fma(e2, s); ws = fmaf(e2, xv.z, ws);
        s = add_via_fma(e3, s); ws = fmaf(e3, xv.w, ws);
    }

    #pragma unroll
    for (int o = 16; o > 0; o >>= 1) {
        s  = add_via_fma(__shfl_xor_sync(0xFFFFFFFFu, s, o), s);
        ws = add_via_fma(__shfl_xor_sync(0xFFFFFFFFu, ws, o), ws);
    }
    if (lane == 0) out[row] = __fdividef(ws, s);
}

__global__ __launch_bounds__(128, 6) void gsm_kernel(
    const float* __restrict__ x,      // [B, M]
    const float* __restrict__ logits, // [N, M]
    const float* __restrict__ gum,    // [B, N, M]
    float* __restrict__ out)          // [B, N]
{
    const int lane = threadIdx.x & 31;
    const int wIn  = threadIdx.x >> 5;

    // Block-contiguous range, warp-strided within the block:
    //  - the block's 4 warps read 4 consecutive rows at any instant
    //    (16 KB contiguous fronts);
    //  - per-warp row counts differ by <=1 chip-wide (balanced tail).
    const int rows = B_ * N_;
    const int base = rows / BLOCKS;           // 147
    const int rem  = rows % BLOCKS;           // 536
    const int bs   = blockIdx.x * base + min((int)blockIdx.x, rem);
    const int be   = bs + base + (blockIdx.x < rem ? 1 : 0);

    const int row0 = bs + wIn;
    if (row0 >= be) return;

    // Register double-buffer: next row's 8 LDG.128 in flight during compute.
    // 24 warps/SM x 8 outstanding LDG.128 = 96 KB/SM continuously in flight.
    float4 bufA[8], bufB[8];
    load_row(bufA, gum, row0, lane);

    int row = row0;
    for (;;) {
        {   // A live, prefetch row+4 into B
            int nxt = row + WARPS_PER_BLOCK;
            load_row(bufB, gum, (nxt < be) ? nxt : row, lane);
            compute_row(bufA, x, logits, out, row, lane);
            row = nxt;
            if (row >= be) break;
        }
        {   // B live, prefetch row+4 into A
            int nxt = row + WARPS_PER_BLOCK;
            load_row(bufA, gum, (nxt < be) ? nxt : row, lane);
            compute_row(bufB, x, logits, out, row, lane);
            row = nxt;
            if (row >= be) break;
        }
    }
}

extern "C" void kernel_launch(void* const* d_in, const int* in_sizes, int n_in,
                              void* d_out, int out_size) {
    // Identify inputs by element count (all three distinct):
    //   input  [B, M]    = 262144
    //   logits [N, M]    = 524288
    //   gumbel [B, N, M] = 134217728
    const float* x = nullptr;
    const float* logits = nullptr;
    const float* gum = nullptr;
    for (int i = 0; i < n_in; ++i) {
        if (in_sizes[i] == B_ * M_)       x      = (const float*)d_in[i];
        else if (in_sizes[i] == N_ * M_)  logits = (const float*)d_in[i];
        else                              gum    = (const float*)d_in[i];
    }

    // Single launch.
    gsm_kernel<<<BLOCKS, 128>>>(x, logits, gum, (float*)d_out);
}